// round 12
// baseline (speedup 1.0000x reference)
#include <cuda_runtime.h>
#include <cuda_fp16.h>
#include <stdint.h>
#include <math.h>

#define NN 100000
#define EE 3200000
#define DD 256
#define LN_EPS 1e-5f
#define NBLK 391              // ceil(NN/256)

// ---------------- scratch (static device globals; no runtime alloc) ----------
__device__ __align__(16) float  g_h  [(size_t)NN * DD];   // h0 = safe(x)
__device__ __align__(16) __half g_xwh[(size_t)NN * DD];   // h @ W (fp16 storage)
__device__ float g_deg[NN];
__device__ float g_dis[NN];
__device__ float g_ew [EE];
__device__ int   g_cnt[NN];
__device__ int   g_rs [NN + 1];
__device__ int   g_cur[NN];
__device__ int   g_bsum[NBLK + 1];
__device__ int   g_boff[NBLK + 1];
__device__ __align__(8) int2 g_edge[EE];  // CSR: {src, nrm bits} grouped by col
__device__ int   g_is64;

__device__ __forceinline__ float fsafe(float v) { return isfinite(v) ? v : 0.0f; }

// ---------------- edge-index dtype detection --------------------------------
__global__ void k_detect(const void* ei) {
    const long long* p = (const long long*)ei;
    int ok64 = 1;
    for (int i = 0; i < 64; i++) {
        long long v = p[i];
        if (v < 0 || v >= NN) ok64 = 0;
    }
    g_is64 = ok64;
}

// ---------------- prep -------------------------------------------------------
__global__ void k_zero() {
    int i = blockIdx.x * blockDim.x + threadIdx.x;
    if (i < NN) { g_deg[i] = 0.0f; g_cnt[i] = 0; }
}

__global__ void k_deg(const void* __restrict__ ei, const float* __restrict__ ew) {
    long long e = (long long)blockIdx.x * blockDim.x + threadIdx.x;
    if (e >= EE) return;
    int is64 = g_is64;
    float w = fsafe(ew[e]);
    w = fmaxf(fabsf(w), 1e-6f);
    g_ew[e] = w;
    int col = is64 ? (int)((const long long*)ei)[(long long)EE + e]
                   : ((const int*)ei)[EE + e];
    atomicAdd(&g_deg[col], w);
    atomicAdd(&g_cnt[col], 1);
}

__global__ void k_dis() {
    int i = blockIdx.x * blockDim.x + threadIdx.x;
    if (i < NN) g_dis[i] = rsqrtf(g_deg[i] + 1.0f);
}

// ---- multi-block exclusive scan of g_cnt: bsum -> scan(sums) -> scatter ----
__global__ __launch_bounds__(256) void k_bsum() {
    int b = blockIdx.x, t = threadIdx.x;
    int i = b * 256 + t;
    int v = (i < NN) ? g_cnt[i] : 0;
#pragma unroll
    for (int o = 16; o > 0; o >>= 1) v += __shfl_xor_sync(0xFFFFFFFFu, v, o);
    __shared__ int ws[8];
    if ((t & 31) == 0) ws[t >> 5] = v;
    __syncthreads();
    if (t == 0) {
        int s = 0;
#pragma unroll
        for (int k = 0; k < 8; k++) s += ws[k];
        g_bsum[b] = s;
    }
}

__global__ __launch_bounds__(512) void k_scan_b() {
    __shared__ int sh[512];
    int t = threadIdx.x;
    int v = (t < NBLK) ? g_bsum[t] : 0;
    sh[t] = v;
    __syncthreads();
#pragma unroll
    for (int o = 1; o < 512; o <<= 1) {
        int n = (t >= o) ? sh[t - o] : 0;
        __syncthreads();
        sh[t] += n;
        __syncthreads();
    }
    if (t < NBLK) g_boff[t] = sh[t] - v;       // exclusive
    if (t == NBLK - 1) g_rs[NN] = sh[t];       // total
}

__global__ __launch_bounds__(256) void k_scan2() {
    int b = blockIdx.x, t = threadIdx.x;
    int lane = t & 31, w = t >> 5;
    int i = b * 256 + t;
    int v = (i < NN) ? g_cnt[i] : 0;
    int incl = v;
#pragma unroll
    for (int o = 1; o < 32; o <<= 1) {
        int n = __shfl_up_sync(0xFFFFFFFFu, incl, o);
        if (lane >= o) incl += n;
    }
    __shared__ int ws[8];
    if (lane == 31) ws[w] = incl;
    __syncthreads();
    if (w == 0 && lane < 8) {
        int s = ws[lane];
#pragma unroll
        for (int o = 1; o < 8; o <<= 1) {
            int n = __shfl_up_sync(0xFFu, s, o);
            if (lane >= o) s += n;
        }
        ws[lane] = s;
    }
    __syncthreads();
    int woff = (w == 0) ? 0 : ws[w - 1];
    int excl = g_boff[b] + woff + incl - v;
    if (i < NN) { g_rs[i] = excl; g_cur[i] = excl; }
}

// fill CSR: packed {src, nrm} per edge grouped by destination (col)
__global__ void k_fill(const void* __restrict__ ei) {
    long long e = (long long)blockIdx.x * blockDim.x + threadIdx.x;
    if (e >= EE) return;
    int is64 = g_is64;
    int row, col;
    if (is64) {
        const long long* p = (const long long*)ei;
        row = (int)p[e]; col = (int)p[(long long)EE + e];
    } else {
        const int* p = (const int*)ei;
        row = p[e]; col = p[EE + e];
    }
    float nrm = g_dis[row] * g_ew[e] * g_dis[col];
    int slot = atomicAdd(&g_cur[col], 1);
    g_edge[slot] = make_int2(row, __float_as_int(nrm));
}

__global__ void k_safe_copy(const float* __restrict__ x) {
    long long i = (long long)blockIdx.x * blockDim.x + threadIdx.x;  // float4 idx
    if (i >= (long long)NN * DD / 4) return;
    float4 v = ((const float4*)x)[i];
    v.x = fsafe(v.x); v.y = fsafe(v.y); v.z = fsafe(v.z); v.w = fsafe(v.w);
    ((float4*)g_h)[i] = v;
}

// ---------------- TF32 tensor-core GEMM: C[M,256] = A[M,256] @ B[256,256] ---
// Block tile 128x64x32, 8 warps (4x2), warp tile 32x32, mma.m16n8k8.tf32.
// Register-prefetch pipeline; C written as fp16.
__device__ __forceinline__ float tf32r(float x) {
    uint32_t u;
    asm("cvt.rna.tf32.f32 %0, %1;" : "=r"(u) : "f"(x));
    return __uint_as_float(u);
}

#define GBM 128
#define GBN 64
#define GBK 32

__global__ __launch_bounds__(256) void k_gemm_tf32(const float* __restrict__ A,
                                                   const float* __restrict__ B,
                                                   __half* __restrict__ C, int M) {
    __shared__ float As[GBM][GBK + 4];
    __shared__ float Bs[GBK][GBN + 4];
    int tid  = threadIdx.x;
    int warp = tid >> 5, lane = tid & 31;
    int wm = warp & 3, wn = warp >> 2;
    int rowbase = blockIdx.x * GBM;
    int colbase = blockIdx.y * GBN;
    int g = lane >> 2, tg = lane & 3;

    int arow = tid >> 3, acol = (tid & 7) * 4;
    int brow = tid >> 4, bcol = (tid & 15) * 4;

    float acc[2][4][4];
#pragma unroll
    for (int a = 0; a < 2; a++)
#pragma unroll
        for (int b = 0; b < 4; b++)
#pragma unroll
            for (int c = 0; c < 4; c++) acc[a][b][c] = 0.0f;

    float4 pa[4], pb[2];
    // prologue fetch k0 = 0
#pragma unroll
    for (int p = 0; p < 4; p++) {
        int gr = rowbase + arow + p * 32;
        pa[p] = (gr < M) ? *(const float4*)&A[(size_t)gr * 256 + acol]
                         : make_float4(0.f, 0.f, 0.f, 0.f);
    }
#pragma unroll
    for (int p = 0; p < 2; p++)
        pb[p] = *(const float4*)&B[(size_t)(brow + p * 16) * 256 + colbase + bcol];

    for (int k0 = 0; k0 < 256; k0 += GBK) {
        // store prefetched tile to smem (convert to tf32)
#pragma unroll
        for (int p = 0; p < 4; p++) {
            float4 a = pa[p];
            a.x = tf32r(a.x); a.y = tf32r(a.y); a.z = tf32r(a.z); a.w = tf32r(a.w);
            *(float4*)&As[arow + p * 32][acol] = a;
        }
#pragma unroll
        for (int p = 0; p < 2; p++) {
            float4 b = pb[p];
            b.x = tf32r(b.x); b.y = tf32r(b.y); b.z = tf32r(b.z); b.w = tf32r(b.w);
            *(float4*)&Bs[brow + p * 16][bcol] = b;
        }
        __syncthreads();

        // prefetch next k-tile (overlaps with mma below)
        if (k0 + GBK < 256) {
            int kn = k0 + GBK;
#pragma unroll
            for (int p = 0; p < 4; p++) {
                int gr = rowbase + arow + p * 32;
                pa[p] = (gr < M) ? *(const float4*)&A[(size_t)gr * 256 + kn + acol]
                                 : make_float4(0.f, 0.f, 0.f, 0.f);
            }
#pragma unroll
            for (int p = 0; p < 2; p++)
                pb[p] = *(const float4*)&B[(size_t)(kn + brow + p * 16) * 256 + colbase + bcol];
        }

#pragma unroll
        for (int kk = 0; kk < GBK; kk += 8) {
            uint32_t afr[2][4];
#pragma unroll
            for (int mt = 0; mt < 2; mt++) {
                int r0 = wm * 32 + mt * 16 + g;
                int c0 = kk + tg;
                afr[mt][0] = __float_as_uint(As[r0][c0]);
                afr[mt][1] = __float_as_uint(As[r0 + 8][c0]);
                afr[mt][2] = __float_as_uint(As[r0][c0 + 4]);
                afr[mt][3] = __float_as_uint(As[r0 + 8][c0 + 4]);
            }
            uint32_t bfr[4][2];
#pragma unroll
            for (int nt = 0; nt < 4; nt++) {
                int c0 = wn * 32 + nt * 8 + g;
                int r0 = kk + tg;
                bfr[nt][0] = __float_as_uint(Bs[r0][c0]);
                bfr[nt][1] = __float_as_uint(Bs[r0 + 4][c0]);
            }
#pragma unroll
            for (int mt = 0; mt < 2; mt++)
#pragma unroll
                for (int nt = 0; nt < 4; nt++) {
                    asm volatile(
                        "mma.sync.aligned.m16n8k8.row.col.f32.tf32.tf32.f32 "
                        "{%0,%1,%2,%3}, {%4,%5,%6,%7}, {%8,%9}, {%0,%1,%2,%3};"
                        : "+f"(acc[mt][nt][0]), "+f"(acc[mt][nt][1]),
                          "+f"(acc[mt][nt][2]), "+f"(acc[mt][nt][3])
                        : "r"(afr[mt][0]), "r"(afr[mt][1]),
                          "r"(afr[mt][2]), "r"(afr[mt][3]),
                          "r"(bfr[nt][0]), "r"(bfr[nt][1]));
                }
        }
        __syncthreads();
    }

#pragma unroll
    for (int mt = 0; mt < 2; mt++) {
#pragma unroll
        for (int half = 0; half < 2; half++) {
            int gr = rowbase + wm * 32 + mt * 16 + g + half * 8;
            if (gr < M) {
#pragma unroll
                for (int nt = 0; nt < 4; nt++) {
                    int gc = colbase + wn * 32 + nt * 8 + tg * 2;
                    __half2 hv = half ? __floats2half2_rn(acc[mt][nt][2], acc[mt][nt][3])
                                      : __floats2half2_rn(acc[mt][nt][0], acc[mt][nt][1]);
                    *(__half2*)&C[(size_t)gr * 256 + gc] = hv;
                }
            }
        }
    }
}

// ---- fused: CSR gather-reduce (fp16 operand, fp32 accum) + self-loop + bias
//      -> safe -> LN -> relu -> + residual. 64 threads/node, 4 nodes/block.
__device__ __forceinline__ void h8_fma(float4& acc, float w, uint2 u) {
    float2 f0 = __half22float2(*reinterpret_cast<__half2*>(&u.x));
    float2 f1 = __half22float2(*reinterpret_cast<__half2*>(&u.y));
    acc.x = fmaf(w, f0.x, acc.x);
    acc.y = fmaf(w, f0.y, acc.y);
    acc.z = fmaf(w, f1.x, acc.z);
    acc.w = fmaf(w, f1.y, acc.w);
}

__global__ __launch_bounds__(256) void k_aggpost(const float* __restrict__ bias,
                                                 const float* __restrict__ lng,
                                                 const float* __restrict__ lnb,
                                                 const float* __restrict__ hres,
                                                 float* __restrict__ out) {
    __shared__ float red[8][2];
    int grp  = threadIdx.x >> 6;
    int lane = threadIdx.x & 63;           // uint2 slot (4 halves) within row
    int node = blockIdx.x * 4 + grp;

    int s = g_rs[node], epd = g_rs[node + 1];
    float d = g_dis[node];
    float self = d * d;
    const uint2* xwh = (const uint2*)g_xwh;   // 64 uint2 per row

    float4 acc;
    {
        uint2 u = xwh[(size_t)node * 64 + lane];
        float2 f0 = __half22float2(*reinterpret_cast<__half2*>(&u.x));
        float2 f1 = __half22float2(*reinterpret_cast<__half2*>(&u.y));
        float4 b = ((const float4*)bias)[lane];
        acc.x = fmaf(self, f0.x, b.x);
        acc.y = fmaf(self, f0.y, b.y);
        acc.z = fmaf(self, f1.x, b.z);
        acc.w = fmaf(self, f1.y, b.w);
    }
    int i = s;
    for (; i + 1 < epd; i += 2) {
        int2 e0 = g_edge[i], e1 = g_edge[i + 1];
        uint2 u0 = xwh[(size_t)e0.x * 64 + lane];
        uint2 u1 = xwh[(size_t)e1.x * 64 + lane];
        h8_fma(acc, __int_as_float(e0.y), u0);
        h8_fma(acc, __int_as_float(e1.y), u1);
    }
    if (i < epd) {
        int2 e0 = g_edge[i];
        uint2 u0 = xwh[(size_t)e0.x * 64 + lane];
        h8_fma(acc, __int_as_float(e0.y), u0);
    }

    acc.x = fsafe(acc.x); acc.y = fsafe(acc.y);
    acc.z = fsafe(acc.z); acc.w = fsafe(acc.w);

    float ss = acc.x + acc.y + acc.z + acc.w;
    float sq = acc.x * acc.x + acc.y * acc.y + acc.z * acc.z + acc.w * acc.w;
#pragma unroll
    for (int o = 16; o > 0; o >>= 1) {
        ss += __shfl_xor_sync(0xFFFFFFFFu, ss, o);
        sq += __shfl_xor_sync(0xFFFFFFFFu, sq, o);
    }
    int bw = threadIdx.x >> 5;
    if ((threadIdx.x & 31) == 0) { red[bw][0] = ss; red[bw][1] = sq; }
    __syncthreads();
    int peer = bw ^ 1;
    ss = red[bw][0] + red[peer][0];
    sq = red[bw][1] + red[peer][1];

    float mu  = ss * (1.0f / 256.0f);
    float var = sq * (1.0f / 256.0f) - mu * mu;
    float inv = rsqrtf(var + LN_EPS);

    float4 gg = ((const float4*)lng)[lane];
    float4 bb = ((const float4*)lnb)[lane];
    float4 rr = ((const float4*)&hres[(size_t)node * DD])[lane];

    float4 o;
    o.x = fsafe(fmaxf(fsafe((acc.x - mu) * inv * gg.x + bb.x), 0.f) + rr.x);
    o.y = fsafe(fmaxf(fsafe((acc.y - mu) * inv * gg.y + bb.y), 0.f) + rr.y);
    o.z = fsafe(fmaxf(fsafe((acc.z - mu) * inv * gg.z + bb.z), 0.f) + rr.z);
    o.w = fsafe(fmaxf(fsafe((acc.w - mu) * inv * gg.w + bb.w), 0.f) + rr.w);

    ((float4*)&out[(size_t)node * DD])[lane] = o;
}

// ---------------- host launch ------------------------------------------------
extern "C" void kernel_launch(void* const* d_in, const int* in_sizes, int n_in,
                              void* d_out, int out_size) {
    const float* x   = (const float*)d_in[0];
    const void*  ei  = d_in[1];
    const float* ew  = (const float*)d_in[2];
    const float* W1  = (const float*)d_in[3];
    const float* b1  = (const float*)d_in[4];
    const float* lg1 = (const float*)d_in[5];
    const float* lb1 = (const float*)d_in[6];
    const float* W2  = (const float*)d_in[7];
    const float* b2  = (const float*)d_in[8];
    const float* lg2 = (const float*)d_in[9];
    const float* lb2 = (const float*)d_in[10];
    float* out = (float*)d_out;

    void *p_h = nullptr, *p_xwh = nullptr;
    cudaGetSymbolAddress(&p_h, g_h);
    cudaGetSymbolAddress(&p_xwh, g_xwh);
    const float* h0 = (const float*)p_h;
    __half* xwh = (__half*)p_xwh;

    const long long nd4 = (long long)NN * DD / 4;

    k_detect<<<1, 1>>>(ei);
    k_zero<<<(NN + 255) / 256, 256>>>();
    k_deg<<<(EE + 255) / 256, 256>>>(ei, ew);
    k_dis<<<(NN + 255) / 256, 256>>>();
    k_bsum<<<NBLK, 256>>>();
    k_scan_b<<<1, 512>>>();
    k_scan2<<<NBLK, 256>>>();
    k_fill<<<(EE + 255) / 256, 256>>>(ei);
    k_safe_copy<<<(int)((nd4 + 255) / 256), 256>>>(x);

    dim3 gemm_grid((NN + GBM - 1) / GBM, 256 / GBN);

    // ---- layer 1 ----
    k_gemm_tf32<<<gemm_grid, 256>>>(h0, W1, xwh, NN);
    k_aggpost<<<NN / 4, 256>>>(b1, lg1, lb1, h0, out);

    // ---- layer 2 ----
    k_gemm_tf32<<<gemm_grid, 256>>>(out, W2, xwh, NN);
    k_aggpost<<<NN / 4, 256>>>(b2, lg2, lb2, out, out);
}

// round 17
// speedup vs baseline: 1.5157x; 1.5157x over previous
#include <cuda_runtime.h>
#include <cuda_fp16.h>
#include <stdint.h>
#include <math.h>

#define NN 100000
#define EE 3200000
#define DD 256
#define LN_EPS 1e-5f
#define NBLK 391              // ceil(NN/256)

// ---------------- scratch (static device globals; no runtime alloc) ----------
__device__ __align__(16) float  g_h  [(size_t)NN * DD];   // h0 = safe(x)
__device__ __align__(16) __half g_xwh[(size_t)NN * DD];   // h @ W (fp16 storage)
__device__ float g_deg[NN];
__device__ float g_dis[NN];
__device__ float g_ew [EE];
__device__ int   g_cnt[NN];
__device__ int   g_rs [NN + 1];
__device__ int   g_cur[NN];
__device__ int   g_bsum[NBLK + 1];
__device__ int   g_boff[NBLK + 1];
__device__ __align__(16) int2 g_edge[EE];  // CSR: {src, nrm bits} grouped by col
__device__ int   g_is64;

__device__ __forceinline__ float fsafe(float v) { return isfinite(v) ? v : 0.0f; }

// ---------------- edge-index dtype detection --------------------------------
__global__ void k_detect(const void* ei) {
    const long long* p = (const long long*)ei;
    int ok64 = 1;
    for (int i = 0; i < 64; i++) {
        long long v = p[i];
        if (v < 0 || v >= NN) ok64 = 0;
    }
    g_is64 = ok64;
}

// ---------------- prep -------------------------------------------------------
__global__ void k_zero() {
    int i = blockIdx.x * blockDim.x + threadIdx.x;
    if (i < NN) { g_deg[i] = 0.0f; g_cnt[i] = 0; }
}

__global__ void k_deg(const void* __restrict__ ei, const float* __restrict__ ew) {
    long long e = (long long)blockIdx.x * blockDim.x + threadIdx.x;
    if (e >= EE) return;
    int is64 = g_is64;
    float w = fsafe(ew[e]);
    w = fmaxf(fabsf(w), 1e-6f);
    g_ew[e] = w;
    int col = is64 ? (int)((const long long*)ei)[(long long)EE + e]
                   : ((const int*)ei)[EE + e];
    atomicAdd(&g_deg[col], w);
    atomicAdd(&g_cnt[col], 1);
}

__global__ void k_dis() {
    int i = blockIdx.x * blockDim.x + threadIdx.x;
    if (i < NN) g_dis[i] = rsqrtf(g_deg[i] + 1.0f);
}

// ---- multi-block exclusive scan of g_cnt: bsum -> scan(sums) -> scatter ----
__global__ __launch_bounds__(256) void k_bsum() {
    int b = blockIdx.x, t = threadIdx.x;
    int i = b * 256 + t;
    int v = (i < NN) ? g_cnt[i] : 0;
#pragma unroll
    for (int o = 16; o > 0; o >>= 1) v += __shfl_xor_sync(0xFFFFFFFFu, v, o);
    __shared__ int ws[8];
    if ((t & 31) == 0) ws[t >> 5] = v;
    __syncthreads();
    if (t == 0) {
        int s = 0;
#pragma unroll
        for (int k = 0; k < 8; k++) s += ws[k];
        g_bsum[b] = s;
    }
}

__global__ __launch_bounds__(512) void k_scan_b() {
    __shared__ int sh[512];
    int t = threadIdx.x;
    int v = (t < NBLK) ? g_bsum[t] : 0;
    sh[t] = v;
    __syncthreads();
#pragma unroll
    for (int o = 1; o < 512; o <<= 1) {
        int n = (t >= o) ? sh[t - o] : 0;
        __syncthreads();
        sh[t] += n;
        __syncthreads();
    }
    if (t < NBLK) g_boff[t] = sh[t] - v;       // exclusive
    if (t == NBLK - 1) g_rs[NN] = sh[t];       // total
}

__global__ __launch_bounds__(256) void k_scan2() {
    int b = blockIdx.x, t = threadIdx.x;
    int lane = t & 31, w = t >> 5;
    int i = b * 256 + t;
    int v = (i < NN) ? g_cnt[i] : 0;
    int incl = v;
#pragma unroll
    for (int o = 1; o < 32; o <<= 1) {
        int n = __shfl_up_sync(0xFFFFFFFFu, incl, o);
        if (lane >= o) incl += n;
    }
    __shared__ int ws[8];
    if (lane == 31) ws[w] = incl;
    __syncthreads();
    if (w == 0 && lane < 8) {
        int s = ws[lane];
#pragma unroll
        for (int o = 1; o < 8; o <<= 1) {
            int n = __shfl_up_sync(0xFFu, s, o);
            if (lane >= o) s += n;
        }
        ws[lane] = s;
    }
    __syncthreads();
    int woff = (w == 0) ? 0 : ws[w - 1];
    int excl = g_boff[b] + woff + incl - v;
    if (i < NN) { g_rs[i] = excl; g_cur[i] = excl; }
}

// fill CSR: packed {src, nrm} per edge grouped by destination (col)
__global__ void k_fill(const void* __restrict__ ei) {
    long long e = (long long)blockIdx.x * blockDim.x + threadIdx.x;
    if (e >= EE) return;
    int is64 = g_is64;
    int row, col;
    if (is64) {
        const long long* p = (const long long*)ei;
        row = (int)p[e]; col = (int)p[(long long)EE + e];
    } else {
        const int* p = (const int*)ei;
        row = p[e]; col = p[EE + e];
    }
    float nrm = g_dis[row] * g_ew[e] * g_dis[col];
    int slot = atomicAdd(&g_cur[col], 1);
    g_edge[slot] = make_int2(row, __float_as_int(nrm));
}

__global__ void k_safe_copy(const float* __restrict__ x) {
    long long i = (long long)blockIdx.x * blockDim.x + threadIdx.x;  // float4 idx
    if (i >= (long long)NN * DD / 4) return;
    float4 v = ((const float4*)x)[i];
    v.x = fsafe(v.x); v.y = fsafe(v.y); v.z = fsafe(v.z); v.w = fsafe(v.w);
    ((float4*)g_h)[i] = v;
}

// ---------------- TF32 tensor-core GEMM: C[M,256] = A[M,256] @ B[256,256] ---
// Block tile 128x64x32, 8 warps (4x2), warp tile 32x32, mma.m16n8k8.tf32.
// Register-prefetch pipeline; C written as fp16.
__device__ __forceinline__ float tf32r(float x) {
    uint32_t u;
    asm("cvt.rna.tf32.f32 %0, %1;" : "=r"(u) : "f"(x));
    return __uint_as_float(u);
}

#define GBM 128
#define GBN 64
#define GBK 32

__global__ __launch_bounds__(256) void k_gemm_tf32(const float* __restrict__ A,
                                                   const float* __restrict__ B,
                                                   __half* __restrict__ C, int M) {
    __shared__ float As[GBM][GBK + 4];
    __shared__ float Bs[GBK][GBN + 4];
    int tid  = threadIdx.x;
    int warp = tid >> 5, lane = tid & 31;
    int wm = warp & 3, wn = warp >> 2;
    int rowbase = blockIdx.x * GBM;
    int colbase = blockIdx.y * GBN;
    int g = lane >> 2, tg = lane & 3;

    int arow = tid >> 3, acol = (tid & 7) * 4;
    int brow = tid >> 4, bcol = (tid & 15) * 4;

    float acc[2][4][4];
#pragma unroll
    for (int a = 0; a < 2; a++)
#pragma unroll
        for (int b = 0; b < 4; b++)
#pragma unroll
            for (int c = 0; c < 4; c++) acc[a][b][c] = 0.0f;

    float4 pa[4], pb[2];
#pragma unroll
    for (int p = 0; p < 4; p++) {
        int gr = rowbase + arow + p * 32;
        pa[p] = (gr < M) ? *(const float4*)&A[(size_t)gr * 256 + acol]
                         : make_float4(0.f, 0.f, 0.f, 0.f);
    }
#pragma unroll
    for (int p = 0; p < 2; p++)
        pb[p] = *(const float4*)&B[(size_t)(brow + p * 16) * 256 + colbase + bcol];

    for (int k0 = 0; k0 < 256; k0 += GBK) {
#pragma unroll
        for (int p = 0; p < 4; p++) {
            float4 a = pa[p];
            a.x = tf32r(a.x); a.y = tf32r(a.y); a.z = tf32r(a.z); a.w = tf32r(a.w);
            *(float4*)&As[arow + p * 32][acol] = a;
        }
#pragma unroll
        for (int p = 0; p < 2; p++) {
            float4 b = pb[p];
            b.x = tf32r(b.x); b.y = tf32r(b.y); b.z = tf32r(b.z); b.w = tf32r(b.w);
            *(float4*)&Bs[brow + p * 16][bcol] = b;
        }
        __syncthreads();

        if (k0 + GBK < 256) {
            int kn = k0 + GBK;
#pragma unroll
            for (int p = 0; p < 4; p++) {
                int gr = rowbase + arow + p * 32;
                pa[p] = (gr < M) ? *(const float4*)&A[(size_t)gr * 256 + kn + acol]
                                 : make_float4(0.f, 0.f, 0.f, 0.f);
            }
#pragma unroll
            for (int p = 0; p < 2; p++)
                pb[p] = *(const float4*)&B[(size_t)(kn + brow + p * 16) * 256 + colbase + bcol];
        }

#pragma unroll
        for (int kk = 0; kk < GBK; kk += 8) {
            uint32_t afr[2][4];
#pragma unroll
            for (int mt = 0; mt < 2; mt++) {
                int r0 = wm * 32 + mt * 16 + g;
                int c0 = kk + tg;
                afr[mt][0] = __float_as_uint(As[r0][c0]);
                afr[mt][1] = __float_as_uint(As[r0 + 8][c0]);
                afr[mt][2] = __float_as_uint(As[r0][c0 + 4]);
                afr[mt][3] = __float_as_uint(As[r0 + 8][c0 + 4]);
            }
            uint32_t bfr[4][2];
#pragma unroll
            for (int nt = 0; nt < 4; nt++) {
                int c0 = wn * 32 + nt * 8 + g;
                int r0 = kk + tg;
                bfr[nt][0] = __float_as_uint(Bs[r0][c0]);
                bfr[nt][1] = __float_as_uint(Bs[r0 + 4][c0]);
            }
#pragma unroll
            for (int mt = 0; mt < 2; mt++)
#pragma unroll
                for (int nt = 0; nt < 4; nt++) {
                    asm volatile(
                        "mma.sync.aligned.m16n8k8.row.col.f32.tf32.tf32.f32 "
                        "{%0,%1,%2,%3}, {%4,%5,%6,%7}, {%8,%9}, {%0,%1,%2,%3};"
                        : "+f"(acc[mt][nt][0]), "+f"(acc[mt][nt][1]),
                          "+f"(acc[mt][nt][2]), "+f"(acc[mt][nt][3])
                        : "r"(afr[mt][0]), "r"(afr[mt][1]),
                          "r"(afr[mt][2]), "r"(afr[mt][3]),
                          "r"(bfr[nt][0]), "r"(bfr[nt][1]));
                }
        }
        __syncthreads();
    }

#pragma unroll
    for (int mt = 0; mt < 2; mt++) {
#pragma unroll
        for (int half = 0; half < 2; half++) {
            int gr = rowbase + wm * 32 + mt * 16 + g + half * 8;
            if (gr < M) {
#pragma unroll
                for (int nt = 0; nt < 4; nt++) {
                    int gc = colbase + wn * 32 + nt * 8 + tg * 2;
                    __half2 hv = half ? __floats2half2_rn(acc[mt][nt][2], acc[mt][nt][3])
                                      : __floats2half2_rn(acc[mt][nt][0], acc[mt][nt][1]);
                    *(__half2*)&C[(size_t)gr * 256 + gc] = hv;
                }
            }
        }
    }
}

// ---- fused: CSR gather-reduce + self-loop + bias -> safe -> LN -> relu -> +res
// ONE warp per node: 32 lanes x uint4 (8 halves) = whole 512B fp16 row per
// warp-request. 8 nodes per 256-thread block; NN = 8 * 12500 exactly.
// Edge records loaded as int2 (8B, always aligned; int4 pair-loads trapped on
// odd CSR segment starts).
__device__ __forceinline__ void h16_fma(float acc[8], float w, uint4 u) {
    float2 a = __half22float2(*reinterpret_cast<__half2*>(&u.x));
    float2 b = __half22float2(*reinterpret_cast<__half2*>(&u.y));
    float2 c = __half22float2(*reinterpret_cast<__half2*>(&u.z));
    float2 d = __half22float2(*reinterpret_cast<__half2*>(&u.w));
    acc[0] = fmaf(w, a.x, acc[0]); acc[1] = fmaf(w, a.y, acc[1]);
    acc[2] = fmaf(w, b.x, acc[2]); acc[3] = fmaf(w, b.y, acc[3]);
    acc[4] = fmaf(w, c.x, acc[4]); acc[5] = fmaf(w, c.y, acc[5]);
    acc[6] = fmaf(w, d.x, acc[6]); acc[7] = fmaf(w, d.y, acc[7]);
}

__global__ __launch_bounds__(256) void k_aggpost(const float* __restrict__ bias,
                                                 const float* __restrict__ lng,
                                                 const float* __restrict__ lnb,
                                                 const float* __restrict__ hres,
                                                 float* __restrict__ out) {
    int warp = threadIdx.x >> 5;
    int lane = threadIdx.x & 31;            // uint4 slot (8 halves) within row
    int node = blockIdx.x * 8 + warp;

    int s = g_rs[node], epd = g_rs[node + 1];
    float d = g_dis[node];
    float self = d * d;
    const uint4* xwh = (const uint4*)g_xwh;   // 32 uint4 per row

    float acc[8];
    {
        uint4 u = xwh[(size_t)node * 32 + lane];
        float4 b0 = ((const float4*)bias)[lane * 2];
        float4 b1 = ((const float4*)bias)[lane * 2 + 1];
        acc[0] = b0.x; acc[1] = b0.y; acc[2] = b0.z; acc[3] = b0.w;
        acc[4] = b1.x; acc[5] = b1.y; acc[6] = b1.z; acc[7] = b1.w;
        h16_fma(acc, self, u);
    }

    int i = s;
    // unroll x4: four int2 edge loads (8B-aligned), 4 row-gathers in flight
    for (; i + 3 < epd; i += 4) {
        int2 e0 = g_edge[i];
        int2 e1 = g_edge[i + 1];
        int2 e2 = g_edge[i + 2];
        int2 e3 = g_edge[i + 3];
        uint4 u0 = xwh[(size_t)e0.x * 32 + lane];
        uint4 u1 = xwh[(size_t)e1.x * 32 + lane];
        uint4 u2 = xwh[(size_t)e2.x * 32 + lane];
        uint4 u3 = xwh[(size_t)e3.x * 32 + lane];
        h16_fma(acc, __int_as_float(e0.y), u0);
        h16_fma(acc, __int_as_float(e1.y), u1);
        h16_fma(acc, __int_as_float(e2.y), u2);
        h16_fma(acc, __int_as_float(e3.y), u3);
    }
    for (; i < epd; i++) {
        int2 e0 = g_edge[i];
        uint4 u0 = xwh[(size_t)e0.x * 32 + lane];
        h16_fma(acc, __int_as_float(e0.y), u0);
    }

    float ss = 0.f, sq = 0.f;
#pragma unroll
    for (int k = 0; k < 8; k++) {
        acc[k] = fsafe(acc[k]);
        ss += acc[k];
        sq += acc[k] * acc[k];
    }
#pragma unroll
    for (int o = 16; o > 0; o >>= 1) {
        ss += __shfl_xor_sync(0xFFFFFFFFu, ss, o);
        sq += __shfl_xor_sync(0xFFFFFFFFu, sq, o);
    }

    float mu  = ss * (1.0f / 256.0f);
    float var = sq * (1.0f / 256.0f) - mu * mu;
    float inv = rsqrtf(var + LN_EPS);

    float4 g0 = ((const float4*)lng)[lane * 2];
    float4 g1 = ((const float4*)lng)[lane * 2 + 1];
    float4 t0 = ((const float4*)lnb)[lane * 2];
    float4 t1 = ((const float4*)lnb)[lane * 2 + 1];
    const float4* hr = (const float4*)&hres[(size_t)node * DD];
    float4 r0 = hr[lane * 2];
    float4 r1 = hr[lane * 2 + 1];

    float gv[8] = {g0.x, g0.y, g0.z, g0.w, g1.x, g1.y, g1.z, g1.w};
    float tv[8] = {t0.x, t0.y, t0.z, t0.w, t1.x, t1.y, t1.z, t1.w};
    float rv[8] = {r0.x, r0.y, r0.z, r0.w, r1.x, r1.y, r1.z, r1.w};

    float ov[8];
#pragma unroll
    for (int k = 0; k < 8; k++)
        ov[k] = fsafe(fmaxf(fsafe((acc[k] - mu) * inv * gv[k] + tv[k]), 0.f) + rv[k]);

    float4* op = (float4*)&out[(size_t)node * DD];
    op[lane * 2]     = make_float4(ov[0], ov[1], ov[2], ov[3]);
    op[lane * 2 + 1] = make_float4(ov[4], ov[5], ov[6], ov[7]);
}

// ---------------- host launch ------------------------------------------------
extern "C" void kernel_launch(void* const* d_in, const int* in_sizes, int n_in,
                              void* d_out, int out_size) {
    const float* x   = (const float*)d_in[0];
    const void*  ei  = d_in[1];
    const float* ew  = (const float*)d_in[2];
    const float* W1  = (const float*)d_in[3];
    const float* b1  = (const float*)d_in[4];
    const float* lg1 = (const float*)d_in[5];
    const float* lb1 = (const float*)d_in[6];
    const float* W2  = (const float*)d_in[7];
    const float* b2  = (const float*)d_in[8];
    const float* lg2 = (const float*)d_in[9];
    const float* lb2 = (const float*)d_in[10];
    float* out = (float*)d_out;

    void *p_h = nullptr, *p_xwh = nullptr;
    cudaGetSymbolAddress(&p_h, g_h);
    cudaGetSymbolAddress(&p_xwh, g_xwh);
    const float* h0 = (const float*)p_h;
    __half* xwh = (__half*)p_xwh;

    const long long nd4 = (long long)NN * DD / 4;

    k_detect<<<1, 1>>>(ei);
    k_zero<<<(NN + 255) / 256, 256>>>();
    k_deg<<<(EE + 255) / 256, 256>>>(ei, ew);
    k_dis<<<(NN + 255) / 256, 256>>>();
    k_bsum<<<NBLK, 256>>>();
    k_scan_b<<<1, 512>>>();
    k_scan2<<<NBLK, 256>>>();
    k_fill<<<(EE + 255) / 256, 256>>>(ei);
    k_safe_copy<<<(int)((nd4 + 255) / 256), 256>>>(x);

    dim3 gemm_grid((NN + GBM - 1) / GBM, 256 / GBN);

    // ---- layer 1 ----
    k_gemm_tf32<<<gemm_grid, 256>>>(h0, W1, xwh, NN);
    k_aggpost<<<NN / 8, 256>>>(b1, lg1, lb1, h0, out);

    // ---- layer 2 ----
    k_gemm_tf32<<<gemm_grid, 256>>>(out, W2, xwh, NN);
    k_aggpost<<<NN / 8, 256>>>(b2, lg2, lb2, out, out);
}